// round 4
// baseline (speedup 1.0000x reference)
#include <cuda_runtime.h>
#include <cuda_fp16.h>
#include <mma.h>

using namespace nvcuda;

#define NN      4096
#define IN_DIM  512
#define H       8
#define D       64
#define HD      512

#define JSPLIT  4
#define ROWT    32
#define JCHUNK  64
#define JRANGE  (NN / JSPLIT)           // 1024
#define NCHUNK  (JRANGE / JCHUNK)       // 16

// ---- k2f smem layout (bytes) ----
#define PLD       72                     // halves per P row (64 + pad), mult of 8
#define PLANE     2312                   // halves per head plane (32*72 + 8): bank-stagger, 16B mult
#define PH_BYTES  (H * PLANE * 2)        // 36992
#define CLD       68                     // floats per conn row (64 + pad)
#define CBUF      (ROWT * CLD)           // floats per conn buffer
#define CONN_OFF  PH_BYTES
#define CONN_BYTES (2 * CBUF * 4)        // 17408
#define TRG_OFF   (CONN_OFF + CONN_BYTES)  // 54400
#define TBUF      (JCHUNK * H)           // float2 per trg buffer (512)
#define TRG_BYTES (2 * TBUF * 8)         // 8192
#define SMEM_BYTES (TRG_OFF + TRG_BYTES) // 62592

// ---------------- device scratch ----------------
__device__ __half g_data_h[NN * IN_DIM];
__device__ __half g_W_h[HD * IN_DIM];
__device__ __half g_V[(size_t)H * NN * D];               // (h, n, d)
__device__ float2 g_srcexp[NN * H];                      // (n,h): {exp(s), exp(.01 s)}
__device__ float2 g_trgexp[NN * H];                      // (n,h): {exp(t), exp(.01 t)}
__device__ float  g_rowpart[JSPLIT * NN * H];            // (js, n, h)
__device__ float  g_opart[(size_t)JSPLIT * H * NN * D];  // 32 MB partials

// ---------------- cp.async helpers ----------------
__device__ __forceinline__ void cp_async16(void* smem_dst, const void* gmem_src) {
    unsigned saddr = (unsigned)__cvta_generic_to_shared(smem_dst);
    asm volatile("cp.async.cg.shared.global [%0], [%1], 16;\n" :: "r"(saddr), "l"(gmem_src));
}
__device__ __forceinline__ void cp_commit() { asm volatile("cp.async.commit_group;\n"); }
template<int N> __device__ __forceinline__ void cp_wait() {
    asm volatile("cp.async.wait_group %0;\n" :: "n"(N));
}

// ---------------- K0: fp32 -> fp16 conversion ----------------
__global__ void k0_convert(const float* __restrict__ data, const float* __restrict__ W) {
    int i = blockIdx.x * blockDim.x + threadIdx.x;
    if (i < NN * IN_DIM) g_data_h[i] = __float2half(data[i]);
    if (i < HD * IN_DIM) g_W_h[i]    = __float2half(W[i]);
}

// ---------------- K1: data1 tile gemm + fused bias/V/src/trg/exp epilogue ----------------
// grid (NN/128, H), 256 threads (8 warps: 4x2 over 128x64 tile)
__global__ __launch_bounds__(256) void k1_gemm(const float* __restrict__ bias,
                                               const float* __restrict__ sp,
                                               const float* __restrict__ tp) {
    __shared__ float s[128 * 68];
    __shared__ float spS[64], tpS[64], bS[64];
    const int n0 = blockIdx.x * 128;
    const int h  = blockIdx.y;
    const int tid = threadIdx.x;
    const int warp = tid >> 5;
    const int wr = (warp >> 1) * 32;
    const int wc = (warp & 1) * 32;

    if (tid < 64) {
        spS[tid] = sp[h * 64 + tid];
        tpS[tid] = tp[h * 64 + tid];
        bS[tid]  = bias[h * 64 + tid];
    }

    wmma::fragment<wmma::accumulator, 16, 16, 16, float> acc[2][2];
    #pragma unroll
    for (int i = 0; i < 2; i++)
        #pragma unroll
        for (int j = 0; j < 2; j++) wmma::fill_fragment(acc[i][j], 0.0f);

    for (int k = 0; k < IN_DIM; k += 16) {
        wmma::fragment<wmma::matrix_a, 16, 16, 16, __half, wmma::row_major> a[2];
        wmma::fragment<wmma::matrix_b, 16, 16, 16, __half, wmma::col_major> b[2];
        #pragma unroll
        for (int i = 0; i < 2; i++)
            wmma::load_matrix_sync(a[i], g_data_h + (size_t)(n0 + wr + i * 16) * IN_DIM + k, IN_DIM);
        #pragma unroll
        for (int j = 0; j < 2; j++)
            wmma::load_matrix_sync(b[j], g_W_h + (size_t)(h * 64 + wc + j * 16) * IN_DIM + k, IN_DIM);
        #pragma unroll
        for (int i = 0; i < 2; i++)
            #pragma unroll
            for (int j = 0; j < 2; j++)
                wmma::mma_sync(acc[i][j], a[i], b[j], acc[i][j]);
    }
    #pragma unroll
    for (int i = 0; i < 2; i++)
        #pragma unroll
        for (int j = 0; j < 2; j++)
            wmma::store_matrix_sync(s + (wr + i * 16) * 68 + wc + j * 16, acc[i][j],
                                    68, wmma::mem_row_major);
    __syncthreads();

    // bias + V pack (fp16); keep biased value in smem for projections
    for (int e = tid; e < 128 * 64; e += 256) {
        int r = e >> 6, d = e & 63;
        float v = s[r * 68 + d] + bS[d];
        s[r * 68 + d] = v;
        g_V[((size_t)h * NN + n0 + r) * D + d] = __float2half(v);
    }
    __syncthreads();

    // src/trg projections: 2 threads per row
    {
        int r = tid >> 1, hf = tid & 1;
        const float* row = s + r * 68 + hf * 32;
        float ss = 0.0f, tt = 0.0f;
        #pragma unroll
        for (int d = 0; d < 32; d++) {
            float v = row[d];
            ss += v * spS[hf * 32 + d];
            tt += v * tpS[hf * 32 + d];
        }
        ss += __shfl_xor_sync(0xffffffffu, ss, 1);
        tt += __shfl_xor_sync(0xffffffffu, tt, 1);
        if (hf == 0) {
            int n = n0 + r;
            g_srcexp[n * H + h] = make_float2(__expf(ss), __expf(0.01f * ss));
            g_trgexp[n * H + h] = make_float2(__expf(tt), __expf(0.01f * tt));
        }
    }
}

// ---------------- K2f: fused scores + PV, factorized exp, cp.async pipelined ----------------
// grid (NN/32, JSPLIT) = (128, 4), 256 threads (8 warps, 1 per head), 2 CTAs/SM
__global__ __launch_bounds__(256, 2) void k2f_fused(const float* __restrict__ conn) {
    extern __shared__ char sm[];
    __half* Ph    = (__half*)sm;
    float*  connS = (float*)(sm + CONN_OFF);
    float2* trgS  = (float2*)(sm + TRG_OFF);

    const int i0    = blockIdx.x * ROWT;
    const int jbase = blockIdx.y * JRANGE;
    const int tid   = threadIdx.x;
    const int h_m   = tid >> 5;          // mma-phase head (warp id)
    const int h_c   = tid & 7;           // compute-phase head
    const int i_c   = tid >> 3;          // compute-phase row (0..31)

    const float2 A = g_srcexp[(i0 + i_c) * H + h_c];
    float rsum = 0.0f;

    wmma::fragment<wmma::accumulator, 16, 16, 16, float> acc[2][4];
    #pragma unroll
    for (int it = 0; it < 2; it++)
        #pragma unroll
        for (int nn = 0; nn < 4; nn++) wmma::fill_fragment(acc[it][nn], 0.0f);

    const __half* Vh = g_V + (size_t)h_m * NN * D;

    // prefetch chunk 0
    {
        int j0 = jbase;
        #pragma unroll
        for (int it = 0; it < 2; it++) {
            int idx = tid + it * 256;
            int row = idx >> 4, c4 = (idx & 15) << 2;
            cp_async16(connS + row * CLD + c4, conn + (size_t)(i0 + row) * NN + j0 + c4);
        }
        cp_async16(((float4*)trgS) + tid, ((const float4*)(g_trgexp + (size_t)j0 * H)) + tid);
        cp_commit();
    }

    for (int c = 0; c < NCHUNK; c++) {
        const int buf = c & 1;
        const int j0  = jbase + c * JCHUNK;

        if (c + 1 < NCHUNK) {   // prefetch next chunk into other buffer
            int jn = j0 + JCHUNK;
            int nb = buf ^ 1;
            #pragma unroll
            for (int it = 0; it < 2; it++) {
                int idx = tid + it * 256;
                int row = idx >> 4, c4 = (idx & 15) << 2;
                cp_async16(connS + nb * CBUF + row * CLD + c4,
                           conn + (size_t)(i0 + row) * NN + jn + c4);
            }
            cp_async16(((float4*)(trgS + nb * TBUF)) + tid,
                       ((const float4*)(g_trgexp + (size_t)jn * H)) + tid);
            cp_commit();
            cp_wait<1>();
        } else {
            cp_wait<0>();
        }
        __syncthreads();

        // ---- compute P chunk (factorized exp, no MUFU) ----
        {
            const float2* crow = (const float2*)(connS + buf * CBUF + i_c * CLD);
            const float2* trow = trgS + buf * TBUF;
            __half2* prow = (__half2*)(Ph + h_c * PLANE + i_c * PLD);
            float rs = 0.0f;
            #pragma unroll
            for (int jj = 0; jj < JCHUNK / 2; jj++) {
                float2 cc = crow[jj];
                float2 b0 = trow[(2 * jj) * H + h_c];
                float2 b1 = trow[(2 * jj + 1) * H + h_c];
                float p0 = A.x * b0.x, q0 = A.y * b0.y;
                p0 = (p0 >= 1.0f) ? p0 : q0;
                p0 = (cc.x > -0.5f) ? p0 : 0.0f;
                float p1 = A.x * b1.x, q1 = A.y * b1.y;
                p1 = (p1 >= 1.0f) ? p1 : q1;
                p1 = (cc.y > -0.5f) ? p1 : 0.0f;
                rs += p0 + p1;
                prow[jj] = __floats2half2_rn(p0, p1);
            }
            rsum += rs;
        }
        __syncthreads();

        // ---- mma: Ph[h_m] (32x64) @ V[h_m][j0:j0+64][0:64] ----
        {
            const __half* pbase = Ph + h_m * PLANE;
            #pragma unroll
            for (int k = 0; k < 4; k++) {
                wmma::fragment<wmma::matrix_b, 16, 16, 16, __half, wmma::row_major> b[4];
                #pragma unroll
                for (int nn = 0; nn < 4; nn++)
                    wmma::load_matrix_sync(b[nn], Vh + (size_t)(j0 + k * 16) * D + nn * 16, D);
                #pragma unroll
                for (int it = 0; it < 2; it++) {
                    wmma::fragment<wmma::matrix_a, 16, 16, 16, __half, wmma::row_major> a;
                    wmma::load_matrix_sync(a, pbase + (it * 16) * PLD + k * 16, PLD);
                    #pragma unroll
                    for (int nn = 0; nn < 4; nn++)
                        wmma::mma_sync(acc[it][nn], a, b[nn], acc[it][nn]);
                }
            }
        }
        __syncthreads();
    }

    // ---- epilogue: deterministic partials, no atomics ----
    g_rowpart[blockIdx.y * NN * H + (i0 + i_c) * H + h_c] = rsum;

    float* op = g_opart + (((size_t)blockIdx.y * H + h_m) * NN + i0) * D;
    #pragma unroll
    for (int it = 0; it < 2; it++)
        #pragma unroll
        for (int nn = 0; nn < 4; nn++)
            wmma::store_matrix_sync(op + (size_t)(it * 16) * D + nn * 16,
                                    acc[it][nn], D, wmma::mem_row_major);
}

// ---------------- K4: combine partials, normalize ----------------
__global__ void k4_final(float* __restrict__ out) {
    int idx = blockIdx.x * 256 + threadIdx.x;
    int n = idx >> 9, hd = idx & 511;
    int h = hd >> 6, d = hd & 63;
    float s = 0.0f, rs = 0.0f;
    #pragma unroll
    for (int js = 0; js < JSPLIT; js++) {
        s  += g_opart[(((size_t)js * H + h) * NN + n) * D + d];
        rs += g_rowpart[js * NN * H + n * H + h];
    }
    out[idx] = s / rs;
}

// ---------------- launcher ----------------
extern "C" void kernel_launch(void* const* d_in, const int* in_sizes, int n_in,
                              void* d_out, int out_size) {
    const float* data = (const float*)d_in[0];
    const float* conn = (const float*)d_in[1];
    const float* W    = (const float*)d_in[2];
    const float* b    = (const float*)d_in[3];
    const float* sp   = (const float*)d_in[4];
    const float* tp   = (const float*)d_in[5];
    float* out = (float*)d_out;

    cudaFuncSetAttribute(k2f_fused, cudaFuncAttributeMaxDynamicSharedMemorySize, SMEM_BYTES);

    k0_convert<<<(NN * IN_DIM + 255) / 256, 256>>>(data, W);
    k1_gemm<<<dim3(NN / 128, H), 256>>>(b, sp, tp);
    k2f_fused<<<dim3(NN / ROWT, JSPLIT), 256, SMEM_BYTES>>>(conn);
    k4_final<<<(NN * HD) / 256, 256>>>(out);
}

// round 5
// speedup vs baseline: 1.2674x; 1.2674x over previous
#include <cuda_runtime.h>
#include <cuda_fp16.h>
#include <mma.h>

using namespace nvcuda;

#define NN      4096
#define IN_DIM  512
#define H       8
#define D       64
#define HD      512

#define JSPLIT  4
#define ROWT    64
#define JCHUNK  128
#define JRANGE  (NN / JSPLIT)           // 1024
#define NCHUNK  (JRANGE / JCHUNK)       // 8

// ---- k2f smem layout (bytes) ----
#define PLD       136                    // halves per P row (128 + 8 pad), mult of 8
#define PLANE     8712                   // halves per head plane (64*136 + 8), mult of 8
#define PH_BYTES  (H * PLANE * 2)        // 139392
#define CLD       132                    // floats per conn row (128 + 4 pad)
#define CONN_OFF  PH_BYTES
#define CONN_BYTES (ROWT * CLD * 4)      // 33792 (single buffer)
#define TRG_OFF   (CONN_OFF + CONN_BYTES)
#define TRG_BYTES (JCHUNK * H * 8)       // 8192 (float2 per (j,h))
#define SMEM_BYTES (TRG_OFF + TRG_BYTES) // 181376

// ---------------- device scratch ----------------
__device__ __half g_data_h[NN * IN_DIM];
__device__ __half g_W_h[HD * IN_DIM];
__device__ __half g_V[(size_t)H * NN * D];               // (h, n, d)
__device__ float2 g_srcexp[NN * H];                      // (n,h): {exp(s), exp(.01 s)}
__device__ float2 g_trgexp[NN * H];                      // (n,h): {exp(t), exp(.01 t)}
__device__ float  g_rowpart[JSPLIT * NN * H];            // (js, n, h)
__device__ float  g_opart[(size_t)JSPLIT * H * NN * D];  // 32 MB partials

// ---------------- cp.async helpers ----------------
__device__ __forceinline__ void cp_async16(void* smem_dst, const void* gmem_src) {
    unsigned saddr = (unsigned)__cvta_generic_to_shared(smem_dst);
    asm volatile("cp.async.cg.shared.global [%0], [%1], 16;\n" :: "r"(saddr), "l"(gmem_src));
}
__device__ __forceinline__ void cp_commit() { asm volatile("cp.async.commit_group;\n"); }
template<int N> __device__ __forceinline__ void cp_wait() {
    asm volatile("cp.async.wait_group %0;\n" :: "n"(N));
}

// ---------------- K0: fp32 -> fp16 conversion ----------------
__global__ void k0_convert(const float* __restrict__ data, const float* __restrict__ W) {
    int i = blockIdx.x * blockDim.x + threadIdx.x;
    if (i < NN * IN_DIM) g_data_h[i] = __float2half(data[i]);
    if (i < HD * IN_DIM) g_W_h[i]    = __float2half(W[i]);
}

// ---------------- K1: data1 tile gemm + fused bias/V/src/trg/exp epilogue ----------------
// grid (NN/128, H), 256 threads
__global__ __launch_bounds__(256) void k1_gemm(const float* __restrict__ bias,
                                               const float* __restrict__ sp,
                                               const float* __restrict__ tp) {
    __shared__ float s[128 * 68];
    __shared__ float spS[64], tpS[64], bS[64];
    const int n0 = blockIdx.x * 128;
    const int h  = blockIdx.y;
    const int tid = threadIdx.x;
    const int warp = tid >> 5;
    const int wr = (warp >> 1) * 32;
    const int wc = (warp & 1) * 32;

    if (tid < 64) {
        spS[tid] = sp[h * 64 + tid];
        tpS[tid] = tp[h * 64 + tid];
        bS[tid]  = bias[h * 64 + tid];
    }

    wmma::fragment<wmma::accumulator, 16, 16, 16, float> acc[2][2];
    #pragma unroll
    for (int i = 0; i < 2; i++)
        #pragma unroll
        for (int j = 0; j < 2; j++) wmma::fill_fragment(acc[i][j], 0.0f);

    for (int k = 0; k < IN_DIM; k += 16) {
        wmma::fragment<wmma::matrix_a, 16, 16, 16, __half, wmma::row_major> a[2];
        wmma::fragment<wmma::matrix_b, 16, 16, 16, __half, wmma::col_major> b[2];
        #pragma unroll
        for (int i = 0; i < 2; i++)
            wmma::load_matrix_sync(a[i], g_data_h + (size_t)(n0 + wr + i * 16) * IN_DIM + k, IN_DIM);
        #pragma unroll
        for (int j = 0; j < 2; j++)
            wmma::load_matrix_sync(b[j], g_W_h + (size_t)(h * 64 + wc + j * 16) * IN_DIM + k, IN_DIM);
        #pragma unroll
        for (int i = 0; i < 2; i++)
            #pragma unroll
            for (int j = 0; j < 2; j++)
                wmma::mma_sync(acc[i][j], a[i], b[j], acc[i][j]);
    }
    #pragma unroll
    for (int i = 0; i < 2; i++)
        #pragma unroll
        for (int j = 0; j < 2; j++)
            wmma::store_matrix_sync(s + (wr + i * 16) * 68 + wc + j * 16, acc[i][j],
                                    68, wmma::mem_row_major);
    __syncthreads();

    for (int e = tid; e < 128 * 64; e += 256) {
        int r = e >> 6, d = e & 63;
        float v = s[r * 68 + d] + bS[d];
        s[r * 68 + d] = v;
        g_V[((size_t)h * NN + n0 + r) * D + d] = __float2half(v);
    }
    __syncthreads();

    {
        int r = tid >> 1, hf = tid & 1;
        const float* row = s + r * 68 + hf * 32;
        float ss = 0.0f, tt = 0.0f;
        #pragma unroll
        for (int d = 0; d < 32; d++) {
            float v = row[d];
            ss += v * spS[hf * 32 + d];
            tt += v * tpS[hf * 32 + d];
        }
        ss += __shfl_xor_sync(0xffffffffu, ss, 1);
        tt += __shfl_xor_sync(0xffffffffu, tt, 1);
        if (hf == 0) {
            int n = n0 + r;
            g_srcexp[n * H + h] = make_float2(__expf(ss), __expf(0.01f * ss));
            g_trgexp[n * H + h] = make_float2(__expf(tt), __expf(0.01f * tt));
        }
    }
}

// ---------------- K2f: fused scores + PV, K=128 chunks, cp.async hidden under mma ----------------
// grid (NN/64, JSPLIT) = (64, 4), 512 threads (16 warps, 2 per head)
__global__ __launch_bounds__(512, 1) void k2f_fused(const float* __restrict__ conn) {
    extern __shared__ char sm[];
    __half* Ph    = (__half*)sm;
    float*  connS = (float*)(sm + CONN_OFF);
    float2* trgS  = (float2*)(sm + TRG_OFF);

    const int i0    = blockIdx.x * ROWT;
    const int jbase = blockIdx.y * JRANGE;
    const int tid   = threadIdx.x;
    const int warp  = tid >> 5;
    const int h_c   = tid & 7;           // compute-phase head
    const int i_c   = tid >> 3;          // compute-phase row (0..63)
    const int h_m   = warp >> 1;         // mma-phase head
    const int dh    = (warp & 1) * 32;   // mma-phase d offset

    const float2 A = g_srcexp[(i0 + i_c) * H + h_c];
    float rsum = 0.0f;

    wmma::fragment<wmma::accumulator, 16, 16, 16, float> acc[4][2];
    #pragma unroll
    for (int it = 0; it < 4; it++)
        #pragma unroll
        for (int nn = 0; nn < 2; nn++) wmma::fill_fragment(acc[it][nn], 0.0f);

    const __half* Vh = g_V + (size_t)h_m * NN * D;

    // prefetch chunk 0 (conn 32KB + trg 8KB)
    {
        #pragma unroll
        for (int it = 0; it < 4; it++) {
            int idx = tid + it * 512;
            int row = idx >> 5, c4 = (idx & 31) << 2;
            cp_async16(connS + row * CLD + c4,
                       conn + (size_t)(i0 + row) * NN + jbase + c4);
        }
        cp_async16(((float4*)trgS) + tid,
                   ((const float4*)(g_trgexp + (size_t)jbase * H)) + tid);
        cp_commit();
    }

    for (int c = 0; c < NCHUNK; c++) {
        const int j0 = jbase + c * JCHUNK;

        cp_wait<0>();
        __syncthreads();                 // conn/trg chunk ready; prev mma done (Ph free)

        // ---- compute P chunk: thread (i_c, h_c) covers 128 j ----
        {
            const float2* crow = (const float2*)(connS + i_c * CLD);
            __half2* prow = (__half2*)(Ph + h_c * PLANE + i_c * PLD);
            float rs = 0.0f;
            #pragma unroll 8
            for (int jj = 0; jj < JCHUNK / 2; jj++) {
                float2 cc = crow[jj];
                float2 b0 = trgS[(2 * jj) * H + h_c];
                float2 b1 = trgS[(2 * jj + 1) * H + h_c];
                float p0 = A.x * b0.x, q0 = A.y * b0.y;
                p0 = (p0 >= 1.0f) ? p0 : q0;
                p0 = (cc.x > -0.5f) ? p0 : 0.0f;
                float p1 = A.x * b1.x, q1 = A.y * b1.y;
                p1 = (p1 >= 1.0f) ? p1 : q1;
                p1 = (cc.y > -0.5f) ? p1 : 0.0f;
                rs += p0 + p1;
                prow[jj] = __floats2half2_rn(p0, p1);
            }
            rsum += rs;
        }
        __syncthreads();                 // P ready; conn/trg consumed

        // ---- prefetch next chunk (flies during the mma phase) ----
        if (c + 1 < NCHUNK) {
            int jn = j0 + JCHUNK;
            #pragma unroll
            for (int it = 0; it < 4; it++) {
                int idx = tid + it * 512;
                int row = idx >> 5, c4 = (idx & 31) << 2;
                cp_async16(connS + row * CLD + c4,
                           conn + (size_t)(i0 + row) * NN + jn + c4);
            }
            cp_async16(((float4*)trgS) + tid,
                       ((const float4*)(g_trgexp + (size_t)jn * H)) + tid);
            cp_commit();
        }

        // ---- mma: Ph[h_m] (64x128) @ V[h_m][j0:j0+128][dh:dh+32] ----
        {
            const __half* pbase = Ph + h_m * PLANE;
            #pragma unroll
            for (int k = 0; k < 8; k++) {
                wmma::fragment<wmma::matrix_b, 16, 16, 16, __half, wmma::row_major> b[2];
                #pragma unroll
                for (int nn = 0; nn < 2; nn++)
                    wmma::load_matrix_sync(b[nn],
                        Vh + (size_t)(j0 + k * 16) * D + dh + nn * 16, D);
                #pragma unroll
                for (int it = 0; it < 4; it++) {
                    wmma::fragment<wmma::matrix_a, 16, 16, 16, __half, wmma::row_major> a;
                    wmma::load_matrix_sync(a, pbase + (it * 16) * PLD + k * 16, PLD);
                    #pragma unroll
                    for (int nn = 0; nn < 2; nn++)
                        wmma::mma_sync(acc[it][nn], a, b[nn], acc[it][nn]);
                }
            }
        }
        // loop-top sync protects Ph before next compute phase
    }

    // ---- epilogue: deterministic partials, no atomics ----
    g_rowpart[blockIdx.y * NN * H + (i0 + i_c) * H + h_c] = rsum;

    float* op = g_opart + (((size_t)blockIdx.y * H + h_m) * NN + i0) * D + dh;
    #pragma unroll
    for (int it = 0; it < 4; it++)
        #pragma unroll
        for (int nn = 0; nn < 2; nn++)
            wmma::store_matrix_sync(op + (size_t)(it * 16) * D + nn * 16,
                                    acc[it][nn], D, wmma::mem_row_major);
}

// ---------------- K4: combine partials, normalize ----------------
__global__ void k4_final(float* __restrict__ out) {
    int idx = blockIdx.x * 256 + threadIdx.x;
    int n = idx >> 9, hd = idx & 511;
    int h = hd >> 6, d = hd & 63;
    float s = 0.0f, rs = 0.0f;
    #pragma unroll
    for (int js = 0; js < JSPLIT; js++) {
        s  += g_opart[(((size_t)js * H + h) * NN + n) * D + d];
        rs += g_rowpart[js * NN * H + n * H + h];
    }
    out[idx] = s / rs;
}

// ---------------- launcher ----------------
extern "C" void kernel_launch(void* const* d_in, const int* in_sizes, int n_in,
                              void* d_out, int out_size) {
    const float* data = (const float*)d_in[0];
    const float* conn = (const float*)d_in[1];
    const float* W    = (const float*)d_in[2];
    const float* b    = (const float*)d_in[3];
    const float* sp   = (const float*)d_in[4];
    const float* tp   = (const float*)d_in[5];
    float* out = (float*)d_out;

    cudaFuncSetAttribute(k2f_fused, cudaFuncAttributeMaxDynamicSharedMemorySize, SMEM_BYTES);

    k0_convert<<<(NN * IN_DIM + 255) / 256, 256>>>(data, W);
    k1_gemm<<<dim3(NN / 128, H), 256>>>(b, sp, tp);
    k2f_fused<<<dim3(NN / ROWT, JSPLIT), 512, SMEM_BYTES>>>(conn);
    k4_final<<<(NN * HD) / 256, 256>>>(out);
}

// round 6
// speedup vs baseline: 1.5329x; 1.2095x over previous
#include <cuda_runtime.h>
#include <cuda_fp16.h>
#include <mma.h>

using namespace nvcuda;

#define NN      4096
#define IN_DIM  512
#define H       8
#define D       64
#define HD      512

#define JSPLIT  2
#define ROWT    64
#define JCHUNK  128
#define JRANGE  (NN / JSPLIT)           // 2048
#define NCHUNK  (JRANGE / JCHUNK)       // 16

// ---- k2f smem layout ----
// P: per head plane, rows of 128 halves + 8 pad (PLD2=68 half2), plane stagger +4 half2
#define PLD2      68
#define PLANE2    (64 * PLD2 + 4)                 // 4356 half2
#define PH_BYTES  (H * PLANE2 * 4)                // 139392
#define CONN_OFF  PH_BYTES
#define CLD2      68                              // half2 per conn row (64 + 4 pad)
#define CONN_BYTES (64 * CLD2 * 4)                // 17408
#define TRGB_OFF  (CONN_OFF + CONN_BYTES)
#define TRG_LD2   68
#define TRGT_BYTES (H * TRG_LD2 * 4)              // 2176
#define TRGB01_OFF (TRGB_OFF + TRGT_BYTES)
#define SMEM_BYTES (TRGB01_OFF + TRGT_BYTES)      // 161152

// ---------------- device scratch ----------------
__device__ __half  g_data_h[NN * IN_DIM];
__device__ __half  g_W_h[HD * IN_DIM];
__device__ __half  g_V[(size_t)H * NN * D];       // (h, n, d)
__device__ __half  g_srcb[NN * H];                // exp(s) half
__device__ __half  g_srcb01[NN * H];              // exp(0.01 s)
__device__ __half2 g_trgp[H * (NN / 2)];          // [h][n/2]: {exp(t(2k)), exp(t(2k+1))}
__device__ __half2 g_trgp01[H * (NN / 2)];        // same for exp(0.01 t)
__device__ float   g_rowpart[JSPLIT * NN * H];    // (js, n, h)
__device__ float   g_opart[(size_t)JSPLIT * H * NN * D];  // 16 MB partials

__device__ __forceinline__ __half2 u2h2(unsigned u) { return *(__half2*)&u; }

// ---------------- K0: fp32 -> fp16 conversion ----------------
__global__ void k0_convert(const float* __restrict__ data, const float* __restrict__ W) {
    int i = blockIdx.x * blockDim.x + threadIdx.x;
    if (i < NN * IN_DIM) g_data_h[i] = __float2half(data[i]);
    if (i < HD * IN_DIM) g_W_h[i]    = __float2half(W[i]);
}

// ---------------- K1: data1 tile gemm + fused bias/V/src/trg/exp epilogue ----------------
// grid (NN/128, H), 256 threads
__global__ __launch_bounds__(256) void k1_gemm(const float* __restrict__ bias,
                                               const float* __restrict__ sp,
                                               const float* __restrict__ tp) {
    __shared__ float s[128 * 68];
    __shared__ float spS[64], tpS[64], bS[64];
    const int n0 = blockIdx.x * 128;
    const int h  = blockIdx.y;
    const int tid = threadIdx.x;
    const int warp = tid >> 5;
    const int wr = (warp >> 1) * 32;
    const int wc = (warp & 1) * 32;

    if (tid < 64) {
        spS[tid] = sp[h * 64 + tid];
        tpS[tid] = tp[h * 64 + tid];
        bS[tid]  = bias[h * 64 + tid];
    }

    wmma::fragment<wmma::accumulator, 16, 16, 16, float> acc[2][2];
    #pragma unroll
    for (int i = 0; i < 2; i++)
        #pragma unroll
        for (int j = 0; j < 2; j++) wmma::fill_fragment(acc[i][j], 0.0f);

    for (int k = 0; k < IN_DIM; k += 16) {
        wmma::fragment<wmma::matrix_a, 16, 16, 16, __half, wmma::row_major> a[2];
        wmma::fragment<wmma::matrix_b, 16, 16, 16, __half, wmma::col_major> b[2];
        #pragma unroll
        for (int i = 0; i < 2; i++)
            wmma::load_matrix_sync(a[i], g_data_h + (size_t)(n0 + wr + i * 16) * IN_DIM + k, IN_DIM);
        #pragma unroll
        for (int j = 0; j < 2; j++)
            wmma::load_matrix_sync(b[j], g_W_h + (size_t)(h * 64 + wc + j * 16) * IN_DIM + k, IN_DIM);
        #pragma unroll
        for (int i = 0; i < 2; i++)
            #pragma unroll
            for (int j = 0; j < 2; j++)
                wmma::mma_sync(acc[i][j], a[i], b[j], acc[i][j]);
    }
    #pragma unroll
    for (int i = 0; i < 2; i++)
        #pragma unroll
        for (int j = 0; j < 2; j++)
            wmma::store_matrix_sync(s + (wr + i * 16) * 68 + wc + j * 16, acc[i][j],
                                    68, wmma::mem_row_major);
    __syncthreads();

    for (int e = tid; e < 128 * 64; e += 256) {
        int r = e >> 6, d = e & 63;
        float v = s[r * 68 + d] + bS[d];
        s[r * 68 + d] = v;
        g_V[((size_t)h * NN + n0 + r) * D + d] = __float2half(v);
    }
    __syncthreads();

    {
        int r = tid >> 1, hf = tid & 1;
        const float* row = s + r * 68 + hf * 32;
        float ss = 0.0f, tt = 0.0f;
        #pragma unroll
        for (int d = 0; d < 32; d++) {
            float v = row[d];
            ss += v * spS[hf * 32 + d];
            tt += v * tpS[hf * 32 + d];
        }
        ss += __shfl_xor_sync(0xffffffffu, ss, 1);
        tt += __shfl_xor_sync(0xffffffffu, tt, 1);
        if (hf == 0) {
            int n = n0 + r;
            g_srcb[n * H + h]   = __float2half(__expf(ss));
            g_srcb01[n * H + h] = __float2half(__expf(0.01f * ss));
            ((__half*)g_trgp)[(h * (NN / 2) + (n >> 1)) * 2 + (n & 1)]   = __float2half(__expf(tt));
            ((__half*)g_trgp01)[(h * (NN / 2) + (n >> 1)) * 2 + (n & 1)] = __float2half(__expf(0.01f * tt));
        }
    }
}

// ---------------- K2f: fused scores + PV, half2 compute, mask-staged conn ----------------
// grid (NN/64, JSPLIT) = (64, 2), 512 threads (16 warps, 2 per head)
__global__ __launch_bounds__(512, 1) void k2f_fused(const float* __restrict__ conn) {
    extern __shared__ char sm[];
    __half2* Ph2    = (__half2*)sm;
    __half2* connM  = (__half2*)(sm + CONN_OFF);
    __half2* trgSb  = (__half2*)(sm + TRGB_OFF);
    __half2* trgSb01= (__half2*)(sm + TRGB01_OFF);

    const int i0    = blockIdx.x * ROWT;
    const int jbase = blockIdx.y * JRANGE;
    const int tid   = threadIdx.x;
    const int warp  = tid >> 5;
    const int h_c   = tid & 7;
    const int i_c   = tid >> 3;
    const int h_m   = warp >> 1;
    const int dh    = (warp & 1) * 32;

    const __half2 A2   = __half2half2(g_srcb[(i0 + i_c) * H + h_c]);
    const __half2 A012 = __half2half2(g_srcb01[(i0 + i_c) * H + h_c]);
    float rsumf = 0.0f;

    wmma::fragment<wmma::accumulator, 16, 16, 16, float> acc[4][2];
    #pragma unroll
    for (int it = 0; it < 4; it++)
        #pragma unroll
        for (int nn = 0; nn < 2; nn++) wmma::fill_fragment(acc[it][nn], 0.0f);

    const __half* Vh = g_V + (size_t)h_m * NN * D;

    // staging identities: 4 groups of (row, 4 cols) per thread for conn
    const int srow[1] = {0};  // (silence unused warnings pattern)
    (void)srow;

    // ---- stage chunk 0 (synchronous) ----
    {
        int j0 = jbase;
        #pragma unroll
        for (int it = 0; it < 4; it++) {
            int idx = tid + it * 512;
            int row = idx >> 5, c4 = (idx & 31) << 2;
            float4 cv = *(const float4*)(conn + (size_t)(i0 + row) * NN + j0 + c4);
            __half2 m0 = __floats2half2_rn(cv.x > -0.5f ? 1.0f : 0.0f, cv.y > -0.5f ? 1.0f : 0.0f);
            __half2 m1 = __floats2half2_rn(cv.z > -0.5f ? 1.0f : 0.0f, cv.w > -0.5f ? 1.0f : 0.0f);
            connM[row * CLD2 + (c4 >> 1)]     = m0;
            connM[row * CLD2 + (c4 >> 1) + 1] = m1;
        }
        int hh = tid >> 6, jj = tid & 63;
        trgSb[hh * TRG_LD2 + jj]   = g_trgp[hh * (NN / 2) + (j0 >> 1) + jj];
        trgSb01[hh * TRG_LD2 + jj] = g_trgp01[hh * (NN / 2) + (j0 >> 1) + jj];
    }

    for (int c = 0; c < NCHUNK; c++) {
        const int j0 = jbase + c * JCHUNK;
        __syncthreads();   // stage(c) visible; mma(c-1) done (P free)

        // ---- compute P chunk: half2 math, 128 j per thread ----
        {
            const __half2* crow = connM + i_c * CLD2;
            const __half2* tb   = trgSb + h_c * TRG_LD2;
            const __half2* tb01 = trgSb01 + h_c * TRG_LD2;
            __half2* prow = Ph2 + h_c * PLANE2 + i_c * PLD2;
            __half2 rsum2 = __float2half2_rn(0.0f);
            #pragma unroll 8
            for (int jj = 0; jj < 64; jj += 2) {
                uint2 cc  = *(const uint2*)(crow + jj);
                uint2 bb  = *(const uint2*)(tb + jj);
                uint2 bb1 = *(const uint2*)(tb01 + jj);
                __half2 r0 = __hmul2(u2h2(cc.x),
                             __hmax2(__hmul2(A2, u2h2(bb.x)), __hmul2(A012, u2h2(bb1.x))));
                __half2 r1 = __hmul2(u2h2(cc.y),
                             __hmax2(__hmul2(A2, u2h2(bb.y)), __hmul2(A012, u2h2(bb1.y))));
                rsum2 = __hadd2(rsum2, r0);
                rsum2 = __hadd2(rsum2, r1);
                uint2 out; out.x = *(unsigned*)&r0; out.y = *(unsigned*)&r1;
                *(uint2*)(prow + jj) = out;
            }
            rsumf += __low2float(rsum2) + __high2float(rsum2);
        }
        __syncthreads();   // P ready; conn/trg consumed

        // ---- issue next-chunk loads (retire during mma) ----
        float4 cv[4];
        __half2 tnext, tnext01;
        const bool more = (c + 1 < NCHUNK);
        if (more) {
            int jn = j0 + JCHUNK;
            #pragma unroll
            for (int it = 0; it < 4; it++) {
                int idx = tid + it * 512;
                int row = idx >> 5, c4 = (idx & 31) << 2;
                cv[it] = *(const float4*)(conn + (size_t)(i0 + row) * NN + jn + c4);
            }
            int hh = tid >> 6, jj = tid & 63;
            tnext   = g_trgp[hh * (NN / 2) + (jn >> 1) + jj];
            tnext01 = g_trgp01[hh * (NN / 2) + (jn >> 1) + jj];
        }

        // ---- mma: Ph[h_m] (64x128) @ V[h_m][j0:+128][dh:+32] ----
        {
            const __half* pbase = (const __half*)(Ph2 + h_m * PLANE2);
            #pragma unroll
            for (int k = 0; k < 8; k++) {
                wmma::fragment<wmma::matrix_b, 16, 16, 16, __half, wmma::row_major> b[2];
                #pragma unroll
                for (int nn = 0; nn < 2; nn++)
                    wmma::load_matrix_sync(b[nn],
                        Vh + (size_t)(j0 + k * 16) * D + dh + nn * 16, D);
                #pragma unroll
                for (int it = 0; it < 4; it++) {
                    wmma::fragment<wmma::matrix_a, 16, 16, 16, __half, wmma::row_major> a;
                    wmma::load_matrix_sync(a, pbase + (it * 16) * (PLD2 * 2) + k * 16, PLD2 * 2);
                    #pragma unroll
                    for (int nn = 0; nn < 2; nn++)
                        wmma::mma_sync(acc[it][nn], a, b[nn], acc[it][nn]);
                }
            }
        }

        // ---- convert + store staged chunk ----
        if (more) {
            #pragma unroll
            for (int it = 0; it < 4; it++) {
                int idx = tid + it * 512;
                int row = idx >> 5, c4 = (idx & 31) << 2;
                __half2 m0 = __floats2half2_rn(cv[it].x > -0.5f ? 1.0f : 0.0f,
                                               cv[it].y > -0.5f ? 1.0f : 0.0f);
                __half2 m1 = __floats2half2_rn(cv[it].z > -0.5f ? 1.0f : 0.0f,
                                               cv[it].w > -0.5f ? 1.0f : 0.0f);
                connM[row * CLD2 + (c4 >> 1)]     = m0;
                connM[row * CLD2 + (c4 >> 1) + 1] = m1;
            }
            int hh = tid >> 6, jj = tid & 63;
            trgSb[hh * TRG_LD2 + jj]   = tnext;
            trgSb01[hh * TRG_LD2 + jj] = tnext01;
        }
    }

    // ---- epilogue: deterministic partials ----
    g_rowpart[blockIdx.y * NN * H + (i0 + i_c) * H + h_c] = rsumf;

    float* op = g_opart + (((size_t)blockIdx.y * H + h_m) * NN + i0) * D + dh;
    #pragma unroll
    for (int it = 0; it < 4; it++)
        #pragma unroll
        for (int nn = 0; nn < 2; nn++)
            wmma::store_matrix_sync(op + (size_t)(it * 16) * D + nn * 16,
                                    acc[it][nn], D, wmma::mem_row_major);
}

// ---------------- K4: combine partials, normalize ----------------
__global__ void k4_final(float* __restrict__ out) {
    int idx = blockIdx.x * 256 + threadIdx.x;
    int n = idx >> 9, hd = idx & 511;
    int h = hd >> 6, d = hd & 63;
    float s = 0.0f, rs = 0.0f;
    #pragma unroll
    for (int js = 0; js < JSPLIT; js++) {
        s  += g_opart[(((size_t)js * H + h) * NN + n) * D + d];
        rs += g_rowpart[js * NN * H + n * H + h];
    }
    out[idx] = s / rs;
}

// ---------------- launcher ----------------
extern "C" void kernel_launch(void* const* d_in, const int* in_sizes, int n_in,
                              void* d_out, int out_size) {
    const float* data = (const float*)d_in[0];
    const float* conn = (const float*)d_in[1];
    const float* W    = (const float*)d_in[2];
    const float* b    = (const float*)d_in[3];
    const float* sp   = (const float*)d_in[4];
    const float* tp   = (const float*)d_in[5];
    float* out = (float*)d_out;

    cudaFuncSetAttribute(k2f_fused, cudaFuncAttributeMaxDynamicSharedMemorySize, SMEM_BYTES);

    k0_convert<<<(NN * IN_DIM + 255) / 256, 256>>>(data, W);
    k1_gemm<<<dim3(NN / 128, H), 256>>>(b, sp, tp);
    k2f_fused<<<dim3(NN / ROWT, JSPLIT), 512, SMEM_BYTES>>>(conn);
    k4_final<<<(NN * HD) / 256, 256>>>(out);
}